// round 1
// baseline (speedup 1.0000x reference)
#include <cuda_runtime.h>
#include <cuda_bf16.h>

// Problem constants (shapes are fixed by the dataset, but we derive E and N
// from in_sizes at launch for safety).
#define NMAX 250000
#define DIM  64

// Scratch (allowed: __device__ globals, no runtime allocation)
__device__ float g_deg[NMAX];
__device__ float g_dinv[NMAX];

// ---------------------------------------------------------------------------
// 1) deg[n] = 1 (self loop)
__global__ void k_init_deg(int n) {
    int i = blockIdx.x * blockDim.x + threadIdx.x;
    if (i < n) g_deg[i] = 1.0f;
}

// 2) deg[row[e]] += 1 over all edges
__global__ void k_count(const int* __restrict__ row, int E) {
    int e = blockIdx.x * blockDim.x + threadIdx.x;
    if (e < E) atomicAdd(&g_deg[row[e]], 1.0f);
}

// 3) dinv[n] = rsqrt(deg[n])   (deg >= 1 always, self loop)
__global__ void k_rsqrt(int n) {
    int i = blockIdx.x * blockDim.x + threadIdx.x;
    if (i < n) g_dinv[i] = rsqrtf(g_deg[i]);
}

// 4) Self-loop init: out[n] = dinv[n]^2 * in[n]  (writes every output element,
//    so the poisoned d_out is fully initialized before atomics accumulate).
//    One thread per float4 (16 threads per node).
__global__ void k_selfloop(const float* __restrict__ in, int in_stride,
                           float* __restrict__ out, int out_stride, int n) {
    int t = blockIdx.x * blockDim.x + threadIdx.x;
    int node = t >> 4;
    int q = t & 15;
    if (node < n) {
        float v = g_dinv[node];
        v *= v;
        float4 f = *(const float4*)(in + (size_t)node * in_stride + q * 4);
        f.x *= v; f.y *= v; f.z *= v; f.w *= v;
        *(float4*)(out + (size_t)node * out_stride + q * 4) = f;
    }
}

// 5) Edge scatter: out[row] += dinv[row]*dinv[col] * in[col]
//    16 threads per edge, one float4 red.global per thread (sm_90+ vector red:
//    4x fewer L2 atomic transactions than scalar atomicAdd).
__global__ void k_edges(const int* __restrict__ row, const int* __restrict__ col,
                        const float* __restrict__ in, int in_stride,
                        float* __restrict__ out, int out_stride, int E) {
    long long t = (long long)blockIdx.x * blockDim.x + threadIdx.x;
    int e = (int)(t >> 4);
    int q = (int)(t & 15);
    if (e < E) {
        int r = __ldg(row + e);
        int c = __ldg(col + e);
        float v = g_dinv[r] * g_dinv[c];
        float4 f = *(const float4*)(in + (size_t)c * in_stride + q * 4);
        float x = f.x * v, y = f.y * v, z = f.z * v, w = f.w * v;
        float* p = out + (size_t)r * out_stride + q * 4;
        asm volatile("red.global.add.v4.f32 [%0], {%1, %2, %3, %4};"
                     :: "l"(p), "f"(x), "f"(y), "f"(z), "f"(w)
                     : "memory");
    }
}

// 6) Trailing copy: feat (= layer-3 result, at column offset 0 of the strided
//    block) duplicated contiguously after all_feat, if out_size includes it.
__global__ void k_copy_final(const float* __restrict__ src, float* __restrict__ dst, int n) {
    int t = blockIdx.x * blockDim.x + threadIdx.x;
    int node = t >> 4;
    int q = t & 15;
    if (node < n) {
        float4 f = *(const float4*)(src + (size_t)node * 192 + q * 4);
        *(float4*)(dst + (size_t)node * 64 + q * 4) = f;
    }
}

extern "C" void kernel_launch(void* const* d_in, const int* in_sizes, int n_in,
                              void* d_out, int out_size) {
    const int* edge_index = (const int*)d_in[0];
    const float* emb      = (const float*)d_in[1];

    const int E = in_sizes[0] / 2;     // edge_index is (2, E) row-major
    const int n = in_sizes[1] / DIM;   // number of nodes

    const int* row = edge_index;
    const int* col = edge_index + E;

    float* out = (float*)d_out;
    // Output layout per node (LAYER_PERM = (2,0,1)):
    //   [0:64)    = feats[2]  (3rd propagation)
    //   [64:128)  = feats[0]  (1st propagation)
    //   [128:192) = feats[1]  (2nd propagation)
    // then, if out_size covers it, feats[2] again, contiguous, at n*192.
    float* f1 = out + 64;    // stride 192
    float* f2 = out + 128;   // stride 192
    float* f3 = out + 0;     // stride 192

    const int B = 256;

    // Degree + normalization
    k_init_deg<<<(n + B - 1) / B, B>>>(n);
    k_count<<<(E + B - 1) / B, B>>>(row, E);
    k_rsqrt<<<(n + B - 1) / B, B>>>(n);

    const int node_threads = n * 16;
    const long long edge_threads = (long long)E * 16;
    const int node_blocks = (node_threads + B - 1) / B;
    const int edge_blocks = (int)((edge_threads + B - 1) / B);

    // Layer 1: emb (stride 64) -> f1 (stride 192)
    k_selfloop<<<node_blocks, B>>>(emb, DIM, f1, 192, n);
    k_edges<<<edge_blocks, B>>>(row, col, emb, DIM, f1, 192, E);

    // Layer 2: f1 -> f2
    k_selfloop<<<node_blocks, B>>>(f1, 192, f2, 192, n);
    k_edges<<<edge_blocks, B>>>(row, col, f1, 192, f2, 192, E);

    // Layer 3: f2 -> f3
    k_selfloop<<<node_blocks, B>>>(f2, 192, f3, 192, n);
    k_edges<<<edge_blocks, B>>>(row, col, f2, 192, f3, 192, E);

    // Second tuple element: final feat, contiguous, if requested by out_size
    if ((long long)out_size >= (long long)n * 256) {
        k_copy_final<<<node_blocks, B>>>(out, out + (size_t)n * 192, n);
    }
}

// round 2
// speedup vs baseline: 1.8219x; 1.8219x over previous
#include <cuda_runtime.h>
#include <cuda_bf16.h>

#define EMAX 4000000
#define NMAX 250001
#define DIM  64

// ---------------- device scratch (no runtime allocation allowed) -----------
__device__ int   g_cnt[NMAX];        // per-row real-edge count
__device__ int   g_rowptr[NMAX];     // exclusive scan (n+1 entries)
__device__ int   g_cursor[NMAX];     // scatter cursors
__device__ float g_dinv[NMAX];       // rsqrt(deg) incl. self loop
__device__ int   g_blocksums[512];   // scan partials
__device__ int2  g_edges[EMAX];      // CSR payload: {col, weight-as-bits}

// ---------------------------------------------------------------------------
__global__ void k_zero_cnt(int n) {
    int i = blockIdx.x * blockDim.x + threadIdx.x;
    if (i < n) g_cnt[i] = 0;
}

__global__ void k_count(const int* __restrict__ row, int E) {
    int e = blockIdx.x * blockDim.x + threadIdx.x;
    if (e < E) atomicAdd(&g_cnt[row[e]], 1);
}

__global__ void k_dinv(int n) {
    int i = blockIdx.x * blockDim.x + threadIdx.x;
    if (i < n) g_dinv[i] = rsqrtf((float)(g_cnt[i] + 1));  // +1 self loop
}

// --- 3-phase exclusive scan of g_cnt into g_rowptr -------------------------
__global__ void k_scan_block(int n) {
    __shared__ int s[1024];
    int i = blockIdx.x * 1024 + threadIdx.x;
    int v = (i < n) ? g_cnt[i] : 0;
    s[threadIdx.x] = v;
    __syncthreads();
    #pragma unroll
    for (int off = 1; off < 1024; off <<= 1) {
        int x = (threadIdx.x >= off) ? s[threadIdx.x - off] : 0;
        __syncthreads();
        s[threadIdx.x] += x;
        __syncthreads();
    }
    if (i < n) g_rowptr[i] = s[threadIdx.x] - v;           // block-exclusive
    if (threadIdx.x == 1023) g_blocksums[blockIdx.x] = s[1023];
}

__global__ void k_scan_tops(int nb) {
    __shared__ int s[512];
    int t = threadIdx.x;
    int v = (t < nb) ? g_blocksums[t] : 0;
    s[t] = v;
    __syncthreads();
    #pragma unroll
    for (int off = 1; off < 512; off <<= 1) {
        int x = (t >= off) ? s[t - off] : 0;
        __syncthreads();
        s[t] += x;
        __syncthreads();
    }
    if (t < nb) g_blocksums[t] = s[t];                     // inclusive
}

__global__ void k_scan_add(int n, int E) {
    int i = blockIdx.x * 1024 + threadIdx.x;
    if (i < n) {
        int off = (blockIdx.x == 0) ? 0 : g_blocksums[blockIdx.x - 1];
        int v = g_rowptr[i] + off;
        g_rowptr[i] = v;
        g_cursor[i] = v;
    }
    if (i == 0) g_rowptr[n] = E;
}

// --- counting-sort scatter: build {col, w} records grouped by row ----------
__global__ void k_scatter(const int* __restrict__ row, const int* __restrict__ col, int E) {
    int e = blockIdx.x * blockDim.x + threadIdx.x;
    if (e < E) {
        int r = row[e], c = col[e];
        int p = atomicAdd(&g_cursor[r], 1);
        float w = g_dinv[r] * g_dinv[c];
        g_edges[p] = make_int2(c, __float_as_int(w));
    }
}

// --- atomic-free warp-per-row SpMM -----------------------------------------
// out[r] = dinv[r]^2 * in[r] + sum_e w_e * in[col_e]
// One warp per row; each lane owns 2 of the 64 columns (float2 -> warp reads
// a contiguous 256B per gathered node). 4-way edge unroll for MLP.
__global__ void __launch_bounds__(256) k_spmm(
        const float* __restrict__ in, int is,
        float* __restrict__ out, int os,
        float* __restrict__ dup, int n) {
    int r    = (blockIdx.x * blockDim.x + threadIdx.x) >> 5;
    int lane = threadIdx.x & 31;
    if (r >= n) return;

    const float* base = in + lane * 2;
    float s = g_dinv[r];
    float2 f0 = __ldg((const float2*)(base + (size_t)r * is));
    float ax = s * s * f0.x;
    float ay = s * s * f0.y;

    int p  = g_rowptr[r];
    int pe = g_rowptr[r + 1];

    for (; p + 3 < pe; p += 4) {
        int2 e0 = __ldg(&g_edges[p]);
        int2 e1 = __ldg(&g_edges[p + 1]);
        int2 e2 = __ldg(&g_edges[p + 2]);
        int2 e3 = __ldg(&g_edges[p + 3]);
        float2 fA = __ldg((const float2*)(base + (size_t)e0.x * is));
        float2 fB = __ldg((const float2*)(base + (size_t)e1.x * is));
        float2 fC = __ldg((const float2*)(base + (size_t)e2.x * is));
        float2 fD = __ldg((const float2*)(base + (size_t)e3.x * is));
        float w0 = __int_as_float(e0.y), w1 = __int_as_float(e1.y);
        float w2 = __int_as_float(e2.y), w3 = __int_as_float(e3.y);
        ax += w0 * fA.x; ay += w0 * fA.y;
        ax += w1 * fB.x; ay += w1 * fB.y;
        ax += w2 * fC.x; ay += w2 * fC.y;
        ax += w3 * fD.x; ay += w3 * fD.y;
    }
    for (; p < pe; p++) {
        int2 e = __ldg(&g_edges[p]);
        float2 f = __ldg((const float2*)(base + (size_t)e.x * is));
        float w = __int_as_float(e.y);
        ax += w * f.x; ay += w * f.y;
    }

    float2 o = make_float2(ax, ay);
    *(float2*)(out + (size_t)r * os + lane * 2) = o;
    if (dup) *(float2*)(dup + (size_t)r * 64 + lane * 2) = o;
}

// ---------------------------------------------------------------------------
extern "C" void kernel_launch(void* const* d_in, const int* in_sizes, int n_in,
                              void* d_out, int out_size) {
    const int* edge_index = (const int*)d_in[0];
    const float* emb      = (const float*)d_in[1];

    const int E = in_sizes[0] / 2;     // edge_index is (2, E) row-major
    const int n = in_sizes[1] / DIM;   // number of nodes

    const int* row = edge_index;
    const int* col = edge_index + E;

    float* out = (float*)d_out;
    // Output layout per node (LAYER_PERM = (2,0,1)):
    //   [0:64)=feats[2], [64:128)=feats[0], [128:192)=feats[1]; then feat
    //   (== feats[2]) again contiguously at n*192 if out_size covers it.
    float* f1 = out + 64;    // stride 192
    float* f2 = out + 128;   // stride 192
    float* f3 = out + 0;     // stride 192
    bool want_dup = ((long long)out_size >= (long long)n * 256);
    float* dup = want_dup ? (out + (size_t)n * 192) : nullptr;

    const int B = 256;
    const int nb_scan = (n + 1023) / 1024;

    // Preprocess: degrees -> dinv -> rowptr -> sorted {col, w} records
    k_zero_cnt<<<(n + B - 1) / B, B>>>(n);
    k_count<<<(E + B - 1) / B, B>>>(row, E);
    k_dinv<<<(n + B - 1) / B, B>>>(n);
    k_scan_block<<<nb_scan, 1024>>>(n);
    k_scan_tops<<<1, 512>>>(nb_scan);
    k_scan_add<<<nb_scan, 1024>>>(n, E);
    k_scatter<<<(E + B - 1) / B, B>>>(row, col, E);

    // 3 SpMM layers (warp per row)
    const int spmm_blocks = (n * 32 + B - 1) / B;
    k_spmm<<<spmm_blocks, B>>>(emb, DIM, f1, 192, nullptr, n);   // layer 1
    k_spmm<<<spmm_blocks, B>>>(f1, 192, f2, 192, nullptr, n);    // layer 2
    k_spmm<<<spmm_blocks, B>>>(f2, 192, f3, 192, dup, n);        // layer 3
}

// round 3
// speedup vs baseline: 1.8940x; 1.0396x over previous
#include <cuda_runtime.h>
#include <cuda_bf16.h>

#define EMAX 4000000
#define NMAX 250001
#define DIM  64

// ---------------- device scratch (no runtime allocation allowed) -----------
__device__ int   g_cnt[NMAX];        // per-row real-edge count
__device__ int   g_rowptr[NMAX];     // exclusive scan (n+1 entries)
__device__ int   g_cursor[NMAX];     // scatter cursors
__device__ float g_dinv[NMAX];       // rsqrt(deg) incl. self loop
__device__ int   g_blocksums[512];   // scan partials
__device__ int2  g_edges[EMAX];      // CSR payload: {col, weight-as-bits}

// ---------------------------------------------------------------------------
__global__ void k_zero_cnt(int n) {
    int i = blockIdx.x * blockDim.x + threadIdx.x;
    if (i < n) g_cnt[i] = 0;
}

__global__ void k_count(const int* __restrict__ row, int E) {
    int e = blockIdx.x * blockDim.x + threadIdx.x;
    if (e < E) atomicAdd(&g_cnt[row[e]], 1);
}

__global__ void k_dinv(int n) {
    int i = blockIdx.x * blockDim.x + threadIdx.x;
    if (i < n) g_dinv[i] = rsqrtf((float)(g_cnt[i] + 1));  // +1 self loop
}

// --- 3-phase exclusive scan of g_cnt into g_rowptr -------------------------
__global__ void k_scan_block(int n) {
    __shared__ int s[1024];
    int i = blockIdx.x * 1024 + threadIdx.x;
    int v = (i < n) ? g_cnt[i] : 0;
    s[threadIdx.x] = v;
    __syncthreads();
    #pragma unroll
    for (int off = 1; off < 1024; off <<= 1) {
        int x = (threadIdx.x >= off) ? s[threadIdx.x - off] : 0;
        __syncthreads();
        s[threadIdx.x] += x;
        __syncthreads();
    }
    if (i < n) g_rowptr[i] = s[threadIdx.x] - v;           // block-exclusive
    if (threadIdx.x == 1023) g_blocksums[blockIdx.x] = s[1023];
}

__global__ void k_scan_tops(int nb) {
    __shared__ int s[512];
    int t = threadIdx.x;
    int v = (t < nb) ? g_blocksums[t] : 0;
    s[t] = v;
    __syncthreads();
    #pragma unroll
    for (int off = 1; off < 512; off <<= 1) {
        int x = (t >= off) ? s[t - off] : 0;
        __syncthreads();
        s[t] += x;
        __syncthreads();
    }
    if (t < nb) g_blocksums[t] = s[t];                     // inclusive
}

__global__ void k_scan_add(int n, int E) {
    int i = blockIdx.x * 1024 + threadIdx.x;
    if (i < n) {
        int off = (blockIdx.x == 0) ? 0 : g_blocksums[blockIdx.x - 1];
        int v = g_rowptr[i] + off;
        g_rowptr[i] = v;
        g_cursor[i] = v;
    }
    if (i == 0) g_rowptr[n] = E;
}

// --- counting-sort scatter: build {col, w} records grouped by row ----------
__global__ void k_scatter(const int* __restrict__ row, const int* __restrict__ col, int E) {
    int e = blockIdx.x * blockDim.x + threadIdx.x;
    if (e < E) {
        int r = row[e], c = col[e];
        int p = atomicAdd(&g_cursor[r], 1);
        float w = g_dinv[r] * g_dinv[c];
        g_edges[p] = make_int2(c, __float_as_int(w));
    }
}

// --- streaming (evict-first) float2 store ----------------------------------
__device__ __forceinline__ void stcs_f2(float* p, float2 v) {
    asm volatile("st.global.cs.v2.f32 [%0], {%1, %2};" :: "l"(p), "f"(v.x), "f"(v.y) : "memory");
}

// --- atomic-free warp-per-row SpMM -----------------------------------------
// out[r] = dinv[r]^2 * in[r] + sum_e w_e * in[col_e]
// One warp per row; each lane owns 2 of the 64 columns (float2 -> warp reads
// a contiguous 256B per gathered node). 8-way edge unroll for deep MLP;
// streaming stores keep the gather-hot input table resident in L2.
__global__ void __launch_bounds__(256) k_spmm(
        const float* __restrict__ in, int is,
        float* __restrict__ out, int os,
        float* __restrict__ dup, int n) {
    int r    = (blockIdx.x * blockDim.x + threadIdx.x) >> 5;
    int lane = threadIdx.x & 31;
    if (r >= n) return;

    const float* base = in + lane * 2;
    float s = g_dinv[r];
    float2 f0 = __ldg((const float2*)(base + (size_t)r * is));
    float ax = s * s * f0.x;
    float ay = s * s * f0.y;

    int p  = g_rowptr[r];
    int pe = g_rowptr[r + 1];

    for (; p + 7 < pe; p += 8) {
        int2 e0 = __ldg(&g_edges[p]);
        int2 e1 = __ldg(&g_edges[p + 1]);
        int2 e2 = __ldg(&g_edges[p + 2]);
        int2 e3 = __ldg(&g_edges[p + 3]);
        int2 e4 = __ldg(&g_edges[p + 4]);
        int2 e5 = __ldg(&g_edges[p + 5]);
        int2 e6 = __ldg(&g_edges[p + 6]);
        int2 e7 = __ldg(&g_edges[p + 7]);
        float2 fA = __ldg((const float2*)(base + (size_t)e0.x * is));
        float2 fB = __ldg((const float2*)(base + (size_t)e1.x * is));
        float2 fC = __ldg((const float2*)(base + (size_t)e2.x * is));
        float2 fD = __ldg((const float2*)(base + (size_t)e3.x * is));
        float2 fE = __ldg((const float2*)(base + (size_t)e4.x * is));
        float2 fF = __ldg((const float2*)(base + (size_t)e5.x * is));
        float2 fG = __ldg((const float2*)(base + (size_t)e6.x * is));
        float2 fH = __ldg((const float2*)(base + (size_t)e7.x * is));
        float w0 = __int_as_float(e0.y), w1 = __int_as_float(e1.y);
        float w2 = __int_as_float(e2.y), w3 = __int_as_float(e3.y);
        float w4 = __int_as_float(e4.y), w5 = __int_as_float(e5.y);
        float w6 = __int_as_float(e6.y), w7 = __int_as_float(e7.y);
        ax += w0 * fA.x; ay += w0 * fA.y;
        ax += w1 * fB.x; ay += w1 * fB.y;
        ax += w2 * fC.x; ay += w2 * fC.y;
        ax += w3 * fD.x; ay += w3 * fD.y;
        ax += w4 * fE.x; ay += w4 * fE.y;
        ax += w5 * fF.x; ay += w5 * fF.y;
        ax += w6 * fG.x; ay += w6 * fG.y;
        ax += w7 * fH.x; ay += w7 * fH.y;
    }
    for (; p < pe; p++) {
        int2 e = __ldg(&g_edges[p]);
        float2 f = __ldg((const float2*)(base + (size_t)e.x * is));
        float w = __int_as_float(e.y);
        ax += w * f.x; ay += w * f.y;
    }

    float2 o = make_float2(ax, ay);
    stcs_f2(out + (size_t)r * os + lane * 2, o);
    if (dup) stcs_f2(dup + (size_t)r * 64 + lane * 2, o);
}

// ---------------------------------------------------------------------------
extern "C" void kernel_launch(void* const* d_in, const int* in_sizes, int n_in,
                              void* d_out, int out_size) {
    const int* edge_index = (const int*)d_in[0];
    const float* emb      = (const float*)d_in[1];

    const int E = in_sizes[0] / 2;     // edge_index is (2, E) row-major
    const int n = in_sizes[1] / DIM;   // number of nodes

    const int* row = edge_index;
    const int* col = edge_index + E;

    float* out = (float*)d_out;
    // Output layout per node (LAYER_PERM = (2,0,1)):
    //   [0:64)=feats[2], [64:128)=feats[0], [128:192)=feats[1]; then feat
    //   (== feats[2]) again contiguously at n*192 if out_size covers it.
    float* f1 = out + 64;    // stride 192
    float* f2 = out + 128;   // stride 192
    float* f3 = out + 0;     // stride 192
    bool want_dup = ((long long)out_size >= (long long)n * 256);
    float* dup = want_dup ? (out + (size_t)n * 192) : nullptr;

    const int B = 256;
    const int nb_scan = (n + 1023) / 1024;

    // Preprocess: degrees -> dinv -> rowptr -> sorted {col, w} records
    k_zero_cnt<<<(n + B - 1) / B, B>>>(n);
    k_count<<<(E + B - 1) / B, B>>>(row, E);
    k_dinv<<<(n + B - 1) / B, B>>>(n);
    k_scan_block<<<nb_scan, 1024>>>(n);
    k_scan_tops<<<1, 512>>>(nb_scan);
    k_scan_add<<<nb_scan, 1024>>>(n, E);
    k_scatter<<<(E + B - 1) / B, B>>>(row, col, E);

    // 3 SpMM layers (warp per row)
    const int spmm_blocks = (n * 32 + B - 1) / B;
    k_spmm<<<spmm_blocks, B>>>(emb, DIM, f1, 192, nullptr, n);   // layer 1
    k_spmm<<<spmm_blocks, B>>>(f1, 192, f2, 192, nullptr, n);    // layer 2
    k_spmm<<<spmm_blocks, B>>>(f2, 192, f3, 192, dup, n);        // layer 3
}

// round 4
// speedup vs baseline: 2.2937x; 1.2110x over previous
#include <cuda_runtime.h>
#include <cuda_bf16.h>

#define EMAX 4000000
#define NMAX 250000
#define DIM  64

// ---------------- device scratch (no runtime allocation allowed) -----------
__device__ int   g_cnt[NMAX];          // per-row real-edge count
__device__ int   g_rowptr[NMAX];       // excl. scan; advanced to row-end by scatter
__device__ float g_dinv[NMAX];         // rsqrt(deg) incl. self loop
__device__ unsigned long long g_desc[512];  // lookback descriptors
__device__ int   g_ecol[EMAX];         // CSR payload: col only (4B)
__device__ float g_xa[(size_t)NMAX * DIM];  // prescaled feature ping
__device__ float g_xb[(size_t)NMAX * DIM];  // prescaled feature pong

#define FLAG_AGG    (1ULL << 62)
#define FLAG_PREFIX (2ULL << 62)
#define VAL_MASK    ((1ULL << 62) - 1)

// ---------------------------------------------------------------------------
__global__ void k_zero(int n) {
    int i = blockIdx.x * blockDim.x + threadIdx.x;
    if (i < n) g_cnt[i] = 0;
    if (i < 512) g_desc[i] = 0ULL;
}

__global__ void k_count(const int* __restrict__ row, int E) {
    int e = blockIdx.x * blockDim.x + threadIdx.x;
    if (e < E) atomicAdd(&g_cnt[row[e]], 1);
}

// --- single-pass exclusive scan (decoupled lookback) + dinv ----------------
__global__ void __launch_bounds__(1024, 2) k_scan(int n) {
    __shared__ int s[1024];
    __shared__ int s_off;
    int b = blockIdx.x;
    int i = b * 1024 + threadIdx.x;
    int v = (i < n) ? g_cnt[i] : 0;
    s[threadIdx.x] = v;
    __syncthreads();
    #pragma unroll
    for (int off = 1; off < 1024; off <<= 1) {
        int x = (threadIdx.x >= off) ? s[threadIdx.x - off] : 0;
        __syncthreads();
        s[threadIdx.x] += x;
        __syncthreads();
    }
    if (threadIdx.x == 0) {
        unsigned long long total = (unsigned long long)s[1023];
        if (b == 0) {
            __threadfence();
            atomicExch(&g_desc[0], FLAG_PREFIX | total);
            s_off = 0;
        } else {
            __threadfence();
            atomicExch(&g_desc[b], FLAG_AGG | total);
            unsigned long long acc = 0;
            int j = b - 1;
            while (true) {
                unsigned long long d = atomicAdd(&g_desc[j], 0ULL);
                unsigned long long f = d >> 62;
                if (f == 2ULL) { acc += (d & VAL_MASK); break; }
                if (f == 1ULL) { acc += (d & VAL_MASK); j--; }
                else __nanosleep(20);
            }
            __threadfence();
            atomicExch(&g_desc[b], FLAG_PREFIX | (acc + total));
            s_off = (int)acc;
        }
    }
    __syncthreads();
    int off0 = s_off;
    if (i < n) {
        g_rowptr[i] = off0 + s[threadIdx.x] - v;   // exclusive prefix
        g_dinv[i]   = rsqrtf((float)(v + 1));      // +1 self loop
    }
}

// --- counting-sort scatter: col-only records; advances g_rowptr to row end -
__global__ void k_scatter(const int* __restrict__ row, const int* __restrict__ col, int E) {
    int e = blockIdx.x * blockDim.x + threadIdx.x;
    if (e < E) {
        int r = row[e];
        int p = atomicAdd(&g_rowptr[r], 1);
        g_ecol[p] = col[e];
    }
}

// --- prescale: x0 = dinv * emb ---------------------------------------------
__global__ void k_prescale(const float* __restrict__ emb, int n) {
    int t = blockIdx.x * blockDim.x + threadIdx.x;
    int node = t >> 4;
    int q = t & 15;
    if (node < n) {
        float s = g_dinv[node];
        float4 f = *(const float4*)(emb + (size_t)node * DIM + q * 4);
        f.x *= s; f.y *= s; f.z *= s; f.w *= s;
        *(float4*)(g_xa + (size_t)node * DIM + q * 4) = f;
    }
}

// --- streaming (evict-first) float2 store ----------------------------------
__device__ __forceinline__ void stcs_f2(float* p, float2 v) {
    asm volatile("st.global.cs.v2.f32 [%0], {%1, %2};" :: "l"(p), "f"(v.x), "f"(v.y) : "memory");
}

// --- atomic-free warp-per-row SpMM on prescaled features -------------------
// out[r] = dinv[r] * (sum_e x[col_e] + x[r]);  xnext[r] = dinv[r] * out[r].
// One warp per row, lane owns 2 of 64 cols. Edge cols loaded 4-at-a-time
// (broadcast LDG.128); inner loop is pure adds.
__global__ void __launch_bounds__(256) k_spmm(
        const float* __restrict__ gx,
        float* __restrict__ out,           // stride 192 (permuted slot)
        float* __restrict__ xnext,         // stride 64 or nullptr
        float* __restrict__ dup,           // stride 64 or nullptr
        int n) {
    int r    = (blockIdx.x * blockDim.x + threadIdx.x) >> 5;
    int lane = threadIdx.x & 31;
    if (r >= n) return;

    const float* base = gx + lane * 2;
    float2 a = __ldg((const float2*)(base + (size_t)r * DIM));  // x[r] (self)
    float ax = a.x, ay = a.y;

    int pe = __ldg(&g_rowptr[r]);              // post-scatter = row end
    int p  = pe - __ldg(&g_cnt[r]);            // row start

    // peel until p is 4-aligned (for LDG.128 on g_ecol)
    while (p < pe && (p & 3)) {
        int c = __ldg(&g_ecol[p]);
        float2 f = __ldg((const float2*)(base + (size_t)c * DIM));
        ax += f.x; ay += f.y;
        p++;
    }
    for (; p + 7 < pe; p += 8) {
        int4 c0 = __ldg((const int4*)&g_ecol[p]);
        int4 c1 = __ldg((const int4*)&g_ecol[p + 4]);
        float2 f0 = __ldg((const float2*)(base + (size_t)c0.x * DIM));
        float2 f1 = __ldg((const float2*)(base + (size_t)c0.y * DIM));
        float2 f2 = __ldg((const float2*)(base + (size_t)c0.z * DIM));
        float2 f3 = __ldg((const float2*)(base + (size_t)c0.w * DIM));
        float2 f4 = __ldg((const float2*)(base + (size_t)c1.x * DIM));
        float2 f5 = __ldg((const float2*)(base + (size_t)c1.y * DIM));
        float2 f6 = __ldg((const float2*)(base + (size_t)c1.z * DIM));
        float2 f7 = __ldg((const float2*)(base + (size_t)c1.w * DIM));
        ax += f0.x + f1.x + f2.x + f3.x + f4.x + f5.x + f6.x + f7.x;
        ay += f0.y + f1.y + f2.y + f3.y + f4.y + f5.y + f6.y + f7.y;
    }
    if (p + 3 < pe) {
        int4 c0 = __ldg((const int4*)&g_ecol[p]);
        float2 f0 = __ldg((const float2*)(base + (size_t)c0.x * DIM));
        float2 f1 = __ldg((const float2*)(base + (size_t)c0.y * DIM));
        float2 f2 = __ldg((const float2*)(base + (size_t)c0.z * DIM));
        float2 f3 = __ldg((const float2*)(base + (size_t)c0.w * DIM));
        ax += f0.x + f1.x + f2.x + f3.x;
        ay += f0.y + f1.y + f2.y + f3.y;
        p += 4;
    }
    for (; p < pe; p++) {
        int c = __ldg(&g_ecol[p]);
        float2 f = __ldg((const float2*)(base + (size_t)c * DIM));
        ax += f.x; ay += f.y;
    }

    float s = g_dinv[r];
    float ox = s * ax, oy = s * ay;
    stcs_f2(out + (size_t)r * 192 + lane * 2, make_float2(ox, oy));
    if (xnext)
        *(float2*)(xnext + (size_t)r * DIM + lane * 2) = make_float2(s * ox, s * oy);
    if (dup)
        stcs_f2(dup + (size_t)r * DIM + lane * 2, make_float2(ox, oy));
}

// ---------------------------------------------------------------------------
extern "C" void kernel_launch(void* const* d_in, const int* in_sizes, int n_in,
                              void* d_out, int out_size) {
    const int* edge_index = (const int*)d_in[0];
    const float* emb      = (const float*)d_in[1];

    const int E = in_sizes[0] / 2;     // edge_index is (2, E) row-major
    const int n = in_sizes[1] / DIM;   // number of nodes

    const int* row = edge_index;
    const int* col = edge_index + E;

    float* out = (float*)d_out;
    // Output layout per node (LAYER_PERM = (2,0,1)):
    //   [0:64)=feats[2], [64:128)=feats[0], [128:192)=feats[1]; then feat
    //   (== feats[2]) again contiguously at n*192 if out_size covers it.
    float* f1 = out + 64;    // stride 192
    float* f2 = out + 128;   // stride 192
    float* f3 = out + 0;     // stride 192
    bool want_dup = ((long long)out_size >= (long long)n * 256);
    float* dup = want_dup ? (out + (size_t)n * 192) : nullptr;

    const int B = 256;

    float* xa; cudaGetSymbolAddress((void**)&xa, g_xa);
    float* xb; cudaGetSymbolAddress((void**)&xb, g_xb);

    // Preprocess
    k_zero<<<(n + B - 1) / B, B>>>(n);                     // 1
    k_count<<<(E + B - 1) / B, B>>>(row, E);               // 2
    k_scan<<<(n + 1023) / 1024, 1024>>>(n);                // 3 (scan + dinv)
    k_scatter<<<(E + B - 1) / B, B>>>(row, col, E);        // 4
    k_prescale<<<(n * 16 + B - 1) / B, B>>>(emb, n);       // 5

    // 3 SpMM layers (warp per row)
    const int spmm_blocks = (n * 32 + B - 1) / B;
    k_spmm<<<spmm_blocks, B>>>(xa, f1, xb, nullptr, n);    // 6: layer 1
    k_spmm<<<spmm_blocks, B>>>(xb, f2, xa, nullptr, n);    // 7: layer 2
    k_spmm<<<spmm_blocks, B>>>(xa, f3, nullptr, dup, n);   // 8: layer 3
}

// round 5
// speedup vs baseline: 2.3346x; 1.0179x over previous
#include <cuda_runtime.h>
#include <cuda_bf16.h>

#define EMAX 4000000
#define NMAX 250000
#define DIM  64

// ---------------- device scratch (no runtime allocation allowed) -----------
__device__ int   g_cnt[NMAX];          // per-row real-edge count
__device__ int   g_rowptr[NMAX];       // excl. scan; advanced to row-end by scatter
__device__ float g_dinv[NMAX];         // rsqrt(deg) incl. self loop
__device__ unsigned long long g_desc[512];  // lookback descriptors
__device__ int   g_ecol[EMAX];         // CSR payload: col only (4B)
__device__ float g_xa[(size_t)NMAX * DIM];  // prescaled feature ping
__device__ float g_xb[(size_t)NMAX * DIM];  // prescaled feature pong

#define FLAG_AGG    (1ULL << 62)
#define FLAG_PREFIX (2ULL << 62)
#define VAL_MASK    ((1ULL << 62) - 1)

// ---------------------------------------------------------------------------
__global__ void k_zero(int n) {
    int i = blockIdx.x * blockDim.x + threadIdx.x;
    if (i < n) g_cnt[i] = 0;
    if (i < 512) g_desc[i] = 0ULL;
}

// 4 edges per thread: LDG.128 row load, 4 independent REDs (no return use).
__global__ void k_count(const int* __restrict__ row, int E) {
    int t = blockIdx.x * blockDim.x + threadIdx.x;
    int e = t * 4;
    if (e + 3 < E) {
        int4 r4 = __ldg((const int4*)(row + e));
        atomicAdd(&g_cnt[r4.x], 1);
        atomicAdd(&g_cnt[r4.y], 1);
        atomicAdd(&g_cnt[r4.z], 1);
        atomicAdd(&g_cnt[r4.w], 1);
    } else {
        for (int i = e; i < E; i++) atomicAdd(&g_cnt[row[i]], 1);
    }
}

// --- single-pass exclusive scan (decoupled lookback) + dinv + prescale -----
__global__ void __launch_bounds__(1024, 1) k_scan(const float* __restrict__ emb, int n) {
    __shared__ int s[1024];
    __shared__ int s_off;
    int b = blockIdx.x;
    int i = b * 1024 + threadIdx.x;
    int v = (i < n) ? g_cnt[i] : 0;
    s[threadIdx.x] = v;
    __syncthreads();
    #pragma unroll
    for (int off = 1; off < 1024; off <<= 1) {
        int x = (threadIdx.x >= off) ? s[threadIdx.x - off] : 0;
        __syncthreads();
        s[threadIdx.x] += x;
        __syncthreads();
    }
    if (threadIdx.x == 0) {
        unsigned long long total = (unsigned long long)s[1023];
        if (b == 0) {
            __threadfence();
            atomicExch(&g_desc[0], FLAG_PREFIX | total);
            s_off = 0;
        } else {
            __threadfence();
            atomicExch(&g_desc[b], FLAG_AGG | total);
            unsigned long long acc = 0;
            int j = b - 1;
            while (true) {
                unsigned long long d = atomicAdd(&g_desc[j], 0ULL);
                unsigned long long f = d >> 62;
                if (f == 2ULL) { acc += (d & VAL_MASK); break; }
                if (f == 1ULL) { acc += (d & VAL_MASK); j--; }
                else __nanosleep(20);
            }
            __threadfence();
            atomicExch(&g_desc[b], FLAG_PREFIX | (acc + total));
            s_off = (int)acc;
        }
    }
    __syncthreads();
    int off0 = s_off;
    float dv = 0.0f;
    if (i < n) {
        g_rowptr[i] = off0 + s[threadIdx.x] - v;   // exclusive prefix
        dv = rsqrtf((float)(v + 1));               // +1 self loop
        g_dinv[i] = dv;
    }
    // Fused prescale: this block covers nodes [b*1024, b*1024+1024).
    // 1024 threads handle 64 nodes per sweep (16 float4 each).
    __syncthreads();
    int node0 = b * 1024;
    for (int sweep = 0; sweep < 16; sweep++) {
        int node = node0 + sweep * 64 + (threadIdx.x >> 4);
        int q = threadIdx.x & 15;
        if (node < n) {
            float sc = g_dinv[node];
            float4 f = __ldg((const float4*)(emb + (size_t)node * DIM + q * 4));
            f.x *= sc; f.y *= sc; f.z *= sc; f.w *= sc;
            *(float4*)(g_xa + (size_t)node * DIM + q * 4) = f;
        }
    }
}

// --- counting-sort scatter: 4 edges/thread, independent atomics ------------
__global__ void k_scatter(const int* __restrict__ row, const int* __restrict__ col, int E) {
    int t = blockIdx.x * blockDim.x + threadIdx.x;
    int e = t * 4;
    if (e + 3 < E) {
        int4 r4 = __ldg((const int4*)(row + e));
        int4 c4 = __ldg((const int4*)(col + e));
        int p0 = atomicAdd(&g_rowptr[r4.x], 1);
        int p1 = atomicAdd(&g_rowptr[r4.y], 1);
        int p2 = atomicAdd(&g_rowptr[r4.z], 1);
        int p3 = atomicAdd(&g_rowptr[r4.w], 1);
        g_ecol[p0] = c4.x;
        g_ecol[p1] = c4.y;
        g_ecol[p2] = c4.z;
        g_ecol[p3] = c4.w;
    } else {
        for (int i = e; i < E; i++) {
            int p = atomicAdd(&g_rowptr[row[i]], 1);
            g_ecol[p] = col[i];
        }
    }
}

// --- streaming (evict-first) float2 store ----------------------------------
__device__ __forceinline__ void stcs_f2(float* p, float2 v) {
    asm volatile("st.global.cs.v2.f32 [%0], {%1, %2};" :: "l"(p), "f"(v.x), "f"(v.y) : "memory");
}

// --- atomic-free warp-per-row SpMM on prescaled features -------------------
// out[r] = dinv[r] * (sum_e x[col_e] + x[r]);  xnext[r] = dinv[r] * out[r].
__global__ void __launch_bounds__(256) k_spmm(
        const float* __restrict__ gx,
        float* __restrict__ out,           // stride 192 (permuted slot)
        float* __restrict__ xnext,         // stride 64 or nullptr
        float* __restrict__ dup,           // stride 64 or nullptr
        int n) {
    int r    = (blockIdx.x * blockDim.x + threadIdx.x) >> 5;
    int lane = threadIdx.x & 31;
    if (r >= n) return;

    const float* base = gx + lane * 2;
    float2 a = __ldg((const float2*)(base + (size_t)r * DIM));  // x[r] (self)
    float ax = a.x, ay = a.y;

    int pe = __ldg(&g_rowptr[r]);              // post-scatter = row end
    int p  = pe - __ldg(&g_cnt[r]);            // row start

    while (p < pe && (p & 3)) {
        int c = __ldg(&g_ecol[p]);
        float2 f = __ldg((const float2*)(base + (size_t)c * DIM));
        ax += f.x; ay += f.y;
        p++;
    }
    for (; p + 7 < pe; p += 8) {
        int4 c0 = __ldg((const int4*)&g_ecol[p]);
        int4 c1 = __ldg((const int4*)&g_ecol[p + 4]);
        float2 f0 = __ldg((const float2*)(base + (size_t)c0.x * DIM));
        float2 f1 = __ldg((const float2*)(base + (size_t)c0.y * DIM));
        float2 f2 = __ldg((const float2*)(base + (size_t)c0.z * DIM));
        float2 f3 = __ldg((const float2*)(base + (size_t)c0.w * DIM));
        float2 f4 = __ldg((const float2*)(base + (size_t)c1.x * DIM));
        float2 f5 = __ldg((const float2*)(base + (size_t)c1.y * DIM));
        float2 f6 = __ldg((const float2*)(base + (size_t)c1.z * DIM));
        float2 f7 = __ldg((const float2*)(base + (size_t)c1.w * DIM));
        ax += f0.x + f1.x + f2.x + f3.x + f4.x + f5.x + f6.x + f7.x;
        ay += f0.y + f1.y + f2.y + f3.y + f4.y + f5.y + f6.y + f7.y;
    }
    if (p + 3 < pe) {
        int4 c0 = __ldg((const int4*)&g_ecol[p]);
        float2 f0 = __ldg((const float2*)(base + (size_t)c0.x * DIM));
        float2 f1 = __ldg((const float2*)(base + (size_t)c0.y * DIM));
        float2 f2 = __ldg((const float2*)(base + (size_t)c0.z * DIM));
        float2 f3 = __ldg((const float2*)(base + (size_t)c0.w * DIM));
        ax += f0.x + f1.x + f2.x + f3.x;
        ay += f0.y + f1.y + f2.y + f3.y;
        p += 4;
    }
    for (; p < pe; p++) {
        int c = __ldg(&g_ecol[p]);
        float2 f = __ldg((const float2*)(base + (size_t)c * DIM));
        ax += f.x; ay += f.y;
    }

    float s = g_dinv[r];
    float ox = s * ax, oy = s * ay;
    stcs_f2(out + (size_t)r * 192 + lane * 2, make_float2(ox, oy));
    if (xnext)
        *(float2*)(xnext + (size_t)r * DIM + lane * 2) = make_float2(s * ox, s * oy);
    if (dup)
        stcs_f2(dup + (size_t)r * DIM + lane * 2, make_float2(ox, oy));
}

// ---------------------------------------------------------------------------
extern "C" void kernel_launch(void* const* d_in, const int* in_sizes, int n_in,
                              void* d_out, int out_size) {
    const int* edge_index = (const int*)d_in[0];
    const float* emb      = (const float*)d_in[1];

    const int E = in_sizes[0] / 2;     // edge_index is (2, E) row-major
    const int n = in_sizes[1] / DIM;   // number of nodes

    const int* row = edge_index;
    const int* col = edge_index + E;

    float* out = (float*)d_out;
    // LAYER_PERM = (2,0,1): [0:64)=feats[2], [64:128)=feats[0], [128:192)=feats[1];
    // then feat (== feats[2]) again contiguously at n*192 if out_size covers it.
    float* f1 = out + 64;    // stride 192
    float* f2 = out + 128;   // stride 192
    float* f3 = out + 0;     // stride 192
    bool want_dup = ((long long)out_size >= (long long)n * 256);
    float* dup = want_dup ? (out + (size_t)n * 192) : nullptr;

    const int B = 256;
    const int q4 = (E + 3) / 4;

    float* xa; cudaGetSymbolAddress((void**)&xa, g_xa);
    float* xb; cudaGetSymbolAddress((void**)&xb, g_xb);

    // Preprocess
    k_zero<<<(n + B - 1) / B, B>>>(n);
    k_count<<<(q4 + B - 1) / B, B>>>(row, E);
    k_scan<<<(n + 1023) / 1024, 1024>>>(emb, n);           // scan + dinv + prescale
    k_scatter<<<(q4 + B - 1) / B, B>>>(row, col, E);

    // 3 SpMM layers (warp per row)
    const int spmm_blocks = (n * 32 + B - 1) / B;
    k_spmm<<<spmm_blocks, B>>>(xa, f1, xb, nullptr, n);    // layer 1
    k_spmm<<<spmm_blocks, B>>>(xb, f2, xa, nullptr, n);    // layer 2
    k_spmm<<<spmm_blocks, B>>>(xa, f3, nullptr, dup, n);   // layer 3
}

// round 10
// speedup vs baseline: 2.5546x; 1.0942x over previous
#include <cuda_runtime.h>
#include <cuda_bf16.h>
#include <cuda_fp16.h>
#include <cstdint>

#define EMAX 4000000
#define NMAX 250000
#define DIM  64

// ---------------- device scratch (no runtime allocation allowed) -----------
__device__ int   g_cnt[NMAX];          // per-row real-edge count
__device__ int   g_rowptr[NMAX];       // excl. scan; advanced to row-end by scatter
__device__ float g_dinv[NMAX];         // rsqrt(deg) incl. self loop
__device__ unsigned long long g_desc[512];  // lookback descriptors
__device__ int   g_ecol[EMAX];         // CSR payload: col only (4B)
__device__ __half2 g_xa[(size_t)NMAX * 32]; // prescaled feature ping (fp16, 128B/row)
__device__ __half2 g_xb[(size_t)NMAX * 32]; // prescaled feature pong

#define FLAG_AGG    (1ULL << 62)
#define FLAG_PREFIX (2ULL << 62)
#define VAL_MASK    ((1ULL << 62) - 1)

// ---------------------------------------------------------------------------
__global__ void k_zero(int n) {
    int i = blockIdx.x * blockDim.x + threadIdx.x;
    if (i < n) g_cnt[i] = 0;
    if (i < 512) g_desc[i] = 0ULL;
}

// 4 edges per thread: LDG.128 row load, 4 independent atomics.
__global__ void k_count(const int* __restrict__ row, int E) {
    int t = blockIdx.x * blockDim.x + threadIdx.x;
    int e = t * 4;
    if (e + 3 < E) {
        int4 r4 = __ldg((const int4*)(row + e));
        atomicAdd(&g_cnt[r4.x], 1);
        atomicAdd(&g_cnt[r4.y], 1);
        atomicAdd(&g_cnt[r4.z], 1);
        atomicAdd(&g_cnt[r4.w], 1);
    } else {
        for (int i = e; i < E; i++) atomicAdd(&g_cnt[row[i]], 1);
    }
}

// --- single-pass exclusive scan (decoupled lookback) + dinv + prescale -----
__global__ void __launch_bounds__(1024, 1) k_scan(const float* __restrict__ emb, int n) {
    __shared__ int s[1024];
    __shared__ int s_off;
    int b = blockIdx.x;
    int i = b * 1024 + threadIdx.x;
    int v = (i < n) ? g_cnt[i] : 0;
    s[threadIdx.x] = v;
    __syncthreads();
    #pragma unroll
    for (int off = 1; off < 1024; off <<= 1) {
        int x = (threadIdx.x >= off) ? s[threadIdx.x - off] : 0;
        __syncthreads();
        s[threadIdx.x] += x;
        __syncthreads();
    }
    if (threadIdx.x == 0) {
        unsigned long long total = (unsigned long long)s[1023];
        if (b == 0) {
            __threadfence();
            atomicExch(&g_desc[0], FLAG_PREFIX | total);
            s_off = 0;
        } else {
            __threadfence();
            atomicExch(&g_desc[b], FLAG_AGG | total);
            unsigned long long acc = 0;
            int j = b - 1;
            while (true) {
                unsigned long long d = atomicAdd(&g_desc[j], 0ULL);
                unsigned long long f = d >> 62;
                if (f == 2ULL) { acc += (d & VAL_MASK); break; }
                if (f == 1ULL) { acc += (d & VAL_MASK); j--; }
                else __nanosleep(20);
            }
            __threadfence();
            atomicExch(&g_desc[b], FLAG_PREFIX | (acc + total));
            s_off = (int)acc;
        }
    }
    __syncthreads();
    if (i < n) {
        g_rowptr[i] = s_off + s[threadIdx.x] - v;  // exclusive prefix
        g_dinv[i]   = rsqrtf((float)(v + 1));      // +1 self loop
    }
    // Fused prescale: x0 = fp16(dinv * emb). This block covers nodes
    // [b*1024, (b+1)*1024); 16 threads per node, each converts 4 floats.
    __syncthreads();
    int node0 = b * 1024;
    for (int sweep = 0; sweep < 16; sweep++) {
        int node = node0 + sweep * 64 + (threadIdx.x >> 4);
        int q = threadIdx.x & 15;
        if (node < n) {
            float sc = g_dinv[node];
            float4 f = __ldg((const float4*)(emb + (size_t)node * DIM + q * 4));
            __half2 h0 = __floats2half2_rn(sc * f.x, sc * f.y);
            __half2 h1 = __floats2half2_rn(sc * f.z, sc * f.w);
            g_xa[(size_t)node * 32 + q * 2]     = h0;
            g_xa[(size_t)node * 32 + q * 2 + 1] = h1;
        }
    }
}

// --- counting-sort scatter: 4 edges/thread ---------------------------------
__global__ void k_scatter(const int* __restrict__ row, const int* __restrict__ col, int E) {
    int t = blockIdx.x * blockDim.x + threadIdx.x;
    int e = t * 4;
    if (e + 3 < E) {
        int4 r4 = __ldg((const int4*)(row + e));
        int4 c4 = __ldg((const int4*)(col + e));
        int p0 = atomicAdd(&g_rowptr[r4.x], 1);
        int p1 = atomicAdd(&g_rowptr[r4.y], 1);
        int p2 = atomicAdd(&g_rowptr[r4.z], 1);
        int p3 = atomicAdd(&g_rowptr[r4.w], 1);
        g_ecol[p0] = c4.x;
        g_ecol[p1] = c4.y;
        g_ecol[p2] = c4.z;
        g_ecol[p3] = c4.w;
    } else {
        for (int i = e; i < E; i++) {
            int p = atomicAdd(&g_rowptr[row[i]], 1);
            g_ecol[p] = col[i];
        }
    }
}

// --- streaming (evict-first) float2 store ----------------------------------
__device__ __forceinline__ void stcs_f2(float* p, float2 v) {
    asm volatile("st.global.cs.v2.f32 [%0], {%1, %2};" :: "l"(p), "f"(v.x), "f"(v.y) : "memory");
}

// --- atomic-free warp-per-row SpMM on fp16 prescaled features --------------
// out[r] = dinv[r] * (sum_e x[col_e] + x[r]);  xnext[r] = fp16(dinv[r]*out[r]).
// One warp per row; each lane owns 2 of 64 cols -> one half2 (4B) per gather,
// so a warp's gather is a single 128B line. fp32 accumulation.
__global__ void __launch_bounds__(256) k_spmm(
        const __half2* __restrict__ gx,
        float* __restrict__ out,           // stride 192 (permuted slot)
        __half2* __restrict__ xnext,       // 32 half2 per row, or nullptr
        float* __restrict__ dup,           // stride 64 fp32, or nullptr
        int n) {
    int r    = (blockIdx.x * blockDim.x + threadIdx.x) >> 5;
    int lane = threadIdx.x & 31;
    if (r >= n) return;

    const __half2* base = gx + lane;
    float2 a = __half22float2(__ldg(base + (size_t)r * 32));  // x[r] (self)
    float ax = a.x, ay = a.y;

    int pe = __ldg(&g_rowptr[r]);              // post-scatter = row end
    int p  = pe - __ldg(&g_cnt[r]);            // row start

    while (p < pe && (p & 3)) {
        int c = __ldg(&g_ecol[p]);
        float2 f = __half22float2(__ldg(base + (size_t)c * 32));
        ax += f.x; ay += f.y;
        p++;
    }
    for (; p + 7 < pe; p += 8) {
        int4 c0 = __ldg((const int4*)&g_ecol[p]);
        int4 c1 = __ldg((const int4*)&g_ecol[p + 4]);
        float2 f0 = __half22float2(__ldg(base + (size_t)c0.x * 32));
        float2 f1 = __half22float2(__ldg(base + (size_t)c0.y * 32));
        float2 f2 = __half22float2(__ldg(base + (size_t)c0.z * 32));
        float2 f3 = __half22float2(__ldg(base + (size_t)c0.w * 32));
        float2 f4 = __half22float2(__ldg(base + (size_t)c1.x * 32));
        float2 f5 = __half22float2(__ldg(base + (size_t)c1.y * 32));
        float2 f6 = __half22float2(__ldg(base + (size_t)c1.z * 32));
        float2 f7 = __half22float2(__ldg(base + (size_t)c1.w * 32));
        ax += f0.x + f1.x + f2.x + f3.x + f4.x + f5.x + f6.x + f7.x;
        ay += f0.y + f1.y + f2.y + f3.y + f4.y + f5.y + f6.y + f7.y;
    }
    if (p + 3 < pe) {
        int4 c0 = __ldg((const int4*)&g_ecol[p]);
        float2 f0 = __half22float2(__ldg(base + (size_t)c0.x * 32));
        float2 f1 = __half22float2(__ldg(base + (size_t)c0.y * 32));
        float2 f2 = __half22float2(__ldg(base + (size_t)c0.z * 32));
        float2 f3 = __half22float2(__ldg(base + (size_t)c0.w * 32));
        ax += f0.x + f1.x + f2.x + f3.x;
        ay += f0.y + f1.y + f2.y + f3.y;
        p += 4;
    }
    for (; p < pe; p++) {
        int c = __ldg(&g_ecol[p]);
        float2 f = __half22float2(__ldg(base + (size_t)c * 32));
        ax += f.x; ay += f.y;
    }

    float s = g_dinv[r];
    float ox = s * ax, oy = s * ay;
    stcs_f2(out + (size_t)r * 192 + lane * 2, make_float2(ox, oy));
    if (xnext)
        xnext[(size_t)r * 32 + lane] = __floats2half2_rn(s * ox, s * oy);
    if (dup)
        stcs_f2(dup + (size_t)r * DIM + lane * 2, make_float2(ox, oy));
}

// ---------------------------------------------------------------------------
extern "C" void kernel_launch(void* const* d_in, const int* in_sizes, int n_in,
                              void* d_out, int out_size) {
    const int* edge_index = (const int*)d_in[0];
    const float* emb      = (const float*)d_in[1];

    const int E = in_sizes[0] / 2;     // edge_index is (2, E) row-major
    const int n = in_sizes[1] / DIM;   // number of nodes

    const int* row = edge_index;
    const int* col = edge_index + E;

    float* out = (float*)d_out;
    // LAYER_PERM = (2,0,1): [0:64)=feats[2], [64:128)=feats[0], [128:192)=feats[1];
    // then feat (== feats[2]) again contiguously at n*192 if out_size covers it.
    float* f1 = out + 64;    // stride 192
    float* f2 = out + 128;   // stride 192
    float* f3 = out + 0;     // stride 192
    bool want_dup = ((long long)out_size >= (long long)n * 256);
    float* dup = want_dup ? (out + (size_t)n * 192) : nullptr;

    const int B = 256;
    const int q4 = (E + 3) / 4;

    __half2* xa; cudaGetSymbolAddress((void**)&xa, g_xa);
    __half2* xb; cudaGetSymbolAddress((void**)&xb, g_xb);

    // Preprocess
    k_zero<<<(n + B - 1) / B, B>>>(n);
    k_count<<<(q4 + B - 1) / B, B>>>(row, E);
    k_scan<<<(n + 1023) / 1024, 1024>>>(emb, n);           // scan + dinv + prescale
    k_scatter<<<(q4 + B - 1) / B, B>>>(row, col, E);

    // 3 SpMM layers (warp per row)
    const int spmm_blocks = (n * 32 + B - 1) / B;
    k_spmm<<<spmm_blocks, B>>>(xa, f1, xb, nullptr, n);    // layer 1
    k_spmm<<<spmm_blocks, B>>>(xb, f2, xa, nullptr, n);    // layer 2
    k_spmm<<<spmm_blocks, B>>>(xa, f3, nullptr, dup, n);   // layer 3
}